// round 2
// baseline (speedup 1.0000x reference)
#include <cuda_runtime.h>
#include <cuda_bf16.h>
#include <stdint.h>

// Problem constants (fixed shapes for this problem instance)
#define NB   8
#define NC   19
#define HW   262144            // 512*512
#define NPIX (NB * HW)         // 2,097,152
#define OHEM_THRESH 0.7f
#define MIN_KEPT_DEFAULT 131072

// ---------------- device scratch (no allocations allowed) ----------------
__device__ float        g_prob[NPIX];
__device__ float        g_loss[NPIX];
__device__ unsigned int g_hist1[65536];   // bits[30:15]
__device__ unsigned int g_hist2[32768];   // bits[14:0]
__device__ unsigned int g_bin1;
__device__ unsigned int g_rank2;
__device__ int          g_nvalid;
__device__ float        g_threshold;
__device__ double       g_sum;
__device__ int          g_cnt;

// ---------------- kernel 0: zero scratch ----------------
__global__ void k_zero() {
    int i = blockIdx.x * blockDim.x + threadIdx.x;
    if (i < 65536) g_hist1[i] = 0u;
    if (i < 32768) g_hist2[i] = 0u;
    if (i == 0) {
        g_sum = 0.0;
        g_cnt = 0;
        g_bin1 = 0u;
        g_rank2 = 0u;
        g_nvalid = 0;
        g_threshold = OHEM_THRESH;
    }
}

// ---------------- kernel 1: softmax gather + prob/loss + level-1 histogram ----------------
__global__ void __launch_bounds__(256) k_pass1(const float* __restrict__ pred,
                                               const int* __restrict__ tgt) {
    int p = blockIdx.x * blockDim.x + threadIdx.x;
    if (p >= NPIX) return;
    int n  = p >> 18;          // / HW
    int hw = p & (HW - 1);
    const float* b = pred + (size_t)n * (NC * HW) + hw;

    float x[NC];
#pragma unroll
    for (int c = 0; c < NC; c++) x[c] = __ldg(&b[c * HW]);

    int t  = tgt[p];
    int tt = (t < 0) ? 0 : t;

    float m = x[0];
#pragma unroll
    for (int c = 1; c < NC; c++) m = fmaxf(m, x[c]);

    float s = 0.0f;
#pragma unroll
    for (int c = 0; c < NC; c++) s += __expf(x[c] - m);

    float xt = x[0];
#pragma unroll
    for (int c = 1; c < NC; c++) xt = (tt == c) ? x[c] : xt;

    float logp = (xt - m) - __logf(s);
    float prob = __expf(logp);
    bool  valid = (t != -1);

    g_prob[p] = valid ? prob : 2.0f;    // sentinel: bin 0x8000, never selected
    g_loss[p] = -logp;

    if (valid) atomicAdd(&g_hist1[__float_as_uint(prob) >> 15], 1u);
}

// ---------------- kernel 2: scan level-1 histogram, find bin + residual rank ----------------
__global__ void k_scan1(const int* __restrict__ min_kept_ptr) {
    __shared__ unsigned s[1024];
    int tid = threadIdx.x;

    unsigned local = 0;
#pragma unroll 8
    for (int i = 0; i < 64; i++) local += g_hist1[(tid << 6) + i];

    s[tid] = local;
    __syncthreads();
    for (int off = 1; off < 1024; off <<= 1) {
        unsigned v = (tid >= off) ? s[tid - off] : 0u;
        __syncthreads();
        s[tid] += v;
        __syncthreads();
    }
    unsigned incl = s[tid];
    unsigned excl = incl - local;
    unsigned total = s[1023];

    if (tid == 0) g_nvalid = (int)total;
    if ((int)total <= 0) {
        if (tid == 0) g_bin1 = 0xFFFFFFFFu;
        return;
    }

    int mk  = min_kept_ptr ? *min_kept_ptr : MIN_KEPT_DEFAULT;
    int idx = min(mk, (int)total - 1);
    if (idx < 0) idx = 0;
    unsigned r = (unsigned)idx;

    if (r >= excl && r < incl) {
        unsigned c = excl;
        for (int i = 0; i < 64; i++) {
            unsigned h = g_hist1[(tid << 6) + i];
            if (r < c + h) { g_bin1 = (unsigned)((tid << 6) + i); g_rank2 = r - c; break; }
            c += h;
        }
    }
}

// ---------------- kernel 3: level-2 histogram over winning bin ----------------
__global__ void __launch_bounds__(256) k_hist2() {
    int p = blockIdx.x * blockDim.x + threadIdx.x;
    if (p >= NPIX) return;
    unsigned b1 = g_bin1;
    unsigned bits = __float_as_uint(g_prob[p]);
    if ((bits >> 15) == b1) atomicAdd(&g_hist2[bits & 0x7FFFu], 1u);
}

// ---------------- kernel 4: scan level-2 histogram, reconstruct exact k-th value ----------------
__global__ void k_scan2() {
    __shared__ unsigned s[1024];
    int tid = threadIdx.x;
    unsigned b1 = g_bin1;

    if (b1 == 0xFFFFFFFFu) {                  // no valid pixels
        if (tid == 0) g_threshold = OHEM_THRESH;
        return;
    }

    unsigned local = 0;
#pragma unroll
    for (int i = 0; i < 32; i++) local += g_hist2[(tid << 5) + i];

    s[tid] = local;
    __syncthreads();
    for (int off = 1; off < 1024; off <<= 1) {
        unsigned v = (tid >= off) ? s[tid - off] : 0u;
        __syncthreads();
        s[tid] += v;
        __syncthreads();
    }
    unsigned incl = s[tid];
    unsigned excl = incl - local;
    unsigned r = g_rank2;

    if (r >= excl && r < incl) {
        unsigned c = excl;
        for (int i = 0; i < 32; i++) {
            unsigned h = g_hist2[(tid << 5) + i];
            if (r < c + h) {
                unsigned bits = (b1 << 15) | (unsigned)((tid << 5) + i);
                g_threshold = fmaxf(__uint_as_float(bits), OHEM_THRESH);
                break;
            }
            c += h;
        }
    }
}

// ---------------- kernel 5: selected sum + count ----------------
__global__ void __launch_bounds__(256) k_reduce() {
    float th = g_threshold;
    double acc = 0.0;
    int    cnt = 0;
    for (int i = blockIdx.x * blockDim.x + threadIdx.x; i < NPIX;
         i += gridDim.x * blockDim.x) {
        float pr = g_prob[i];
        if (pr < th) { acc += (double)g_loss[i]; cnt++; }
    }
    // warp reduce
    for (int off = 16; off > 0; off >>= 1) {
        acc += __shfl_down_sync(0xFFFFFFFFu, acc, off);
        cnt += __shfl_down_sync(0xFFFFFFFFu, cnt, off);
    }
    __shared__ double s_acc[8];
    __shared__ int    s_cnt[8];
    int lane = threadIdx.x & 31, wid = threadIdx.x >> 5;
    if (lane == 0) { s_acc[wid] = acc; s_cnt[wid] = cnt; }
    __syncthreads();
    if (wid == 0) {
        acc = (lane < 8) ? s_acc[lane] : 0.0;
        cnt = (lane < 8) ? s_cnt[lane] : 0;
        for (int off = 4; off > 0; off >>= 1) {
            acc += __shfl_down_sync(0xFFFFFFFFu, acc, off);
            cnt += __shfl_down_sync(0xFFFFFFFFu, cnt, off);
        }
        if (lane == 0) {
            atomicAdd(&g_sum, acc);
            atomicAdd(&g_cnt, cnt);
        }
    }
}

// ---------------- kernel 6: finalize ----------------
__global__ void k_final(float* __restrict__ out) {
    int c = g_cnt;
    out[0] = (float)(g_sum / (double)(c > 0 ? c : 1));
}

// ---------------- launch ----------------
extern "C" void kernel_launch(void* const* d_in, const int* in_sizes, int n_in,
                              void* d_out, int out_size) {
    const float* pred = (const float*)d_in[0];
    const int*   tgt  = (const int*)d_in[1];
    const int*   mk   = (n_in >= 3) ? (const int*)d_in[2] : nullptr;
    float*       out  = (float*)d_out;

    k_zero  <<<256, 256>>>();
    k_pass1 <<<NPIX / 256, 256>>>(pred, tgt);
    k_scan1 <<<1, 1024>>>(mk);
    k_hist2 <<<NPIX / 256, 256>>>();
    k_scan2 <<<1, 1024>>>();
    k_reduce<<<2048, 256>>>();
    k_final <<<1, 1>>>(out);
}